// round 8
// baseline (speedup 1.0000x reference)
#include <cuda_runtime.h>
#include <math.h>

#define Bb   16
#define Nn   1024
#define DIN  32
#define DZ   64
#define DH   64
#define Ff   3
#define Pp   19
#define PPAD 20
#define NEDGE 171
#define ITERS 50
#define ALPHAc 0.1f
#define INV_SCALE (19.0f/1024.0f)

// ---------------- device scratch (static; no allocations) ----------------
// NOTE: every buffer accessed through a >4B vector type is 16B-aligned —
// plain float arrays are only 4B-aligned and wide LDG/STS on them traps.
__device__ __align__(16) float2 g_wpair[(size_t)Bb*Ff*Nn*PPAD]; // softmax POU weights, duplicated {w,w}
__device__ __align__(16) float  g_t[(size_t)192*Pp*Nn];         // stage-1 partials
__device__ __align__(16) float  g_z[(size_t)Bb*Nn*DZ];
__device__ __align__(16) float  g_ffull[(size_t)Bb*Nn*Ff];
__device__ __align__(16) float  g_flat[Bb*Ff*Pp];
__device__ __align__(16) float  g_khat[2*Bb*Ff*Pp*Pp];          // [mat][b][f][p][q]
__device__ __align__(16) float  g_zpb[Bb*DH];
__device__ __align__(16) float  g_uhat[Bb*64];

// packed f32x2 FMA (Blackwell FFMA2)
__device__ __forceinline__ unsigned long long ffma2(unsigned long long a,
                                                    unsigned long long b,
                                                    unsigned long long c) {
    unsigned long long d;
    asm("fma.rn.f32x2 %0, %1, %2, %3;" : "=l"(d) : "l"(a), "l"(b), "l"(c));
    return d;
}
__device__ __forceinline__ float2 ull2f2(unsigned long long v) {
    float2 r;
    asm("mov.b64 {%0,%1}, %2;" : "=f"(r.x), "=f"(r.y) : "l"(v));
    return r;
}

// ---------------- kernel 1: encoder + POU softmax + f_full ----------------
__global__ __launch_bounds__(128) void k_encode(
    const float* __restrict__ tok, const int* __restrict__ dn,
    const float* __restrict__ bv,
    const float* __restrict__ W_enc, const float* __restrict__ b_enc,
    const float* __restrict__ W_src, const float* __restrict__ b_src,
    const float* __restrict__ W_pou)
{
    __shared__ float sWe[DIN*DZ];
    __shared__ float sWp[DZ*57];
    __shared__ float sWs[DZ*Ff];
    __shared__ float sbe[DZ];
    __shared__ float sbs[Ff];
    __shared__ int   sdn[64];
    __shared__ float sbv[64*Ff];

    int b = blockIdx.y;
    int tid = threadIdx.x;
    for (int i = tid; i < DIN*DZ; i += 128) sWe[i] = W_enc[i];
    for (int i = tid; i < DZ*57;  i += 128) sWp[i] = W_pou[i];
    for (int i = tid; i < DZ*Ff;  i += 128) sWs[i] = W_src[i];
    if (tid < DZ) sbe[tid] = b_enc[tid];
    if (tid < Ff) sbs[tid] = b_src[tid];
    if (tid < 64) sdn[tid] = dn[b*64 + tid];
    for (int i = tid; i < 64*Ff; i += 128) sbv[i] = bv[b*64*Ff + i];
    __syncthreads();

    int n = blockIdx.x*128 + tid;

    float x[DIN];
    const float4* xp = (const float4*)(tok + ((size_t)b*Nn + n)*DIN);
    #pragma unroll
    for (int i = 0; i < DIN/4; i++) {
        float4 v = xp[i];
        x[4*i] = v.x; x[4*i+1] = v.y; x[4*i+2] = v.z; x[4*i+3] = v.w;
    }

    float z[DZ];
    #pragma unroll
    for (int d = 0; d < DZ; d++) z[d] = sbe[d];
    for (int k = 0; k < DIN; k++) {
        float xv = x[k];
        const float* wr = sWe + k*DZ;
        #pragma unroll
        for (int d = 0; d < DZ; d++) z[d] += xv * wr[d];
    }
    #pragma unroll
    for (int d = 0; d < DZ; d++) z[d] = tanhf(z[d]);

    float4* zo = (float4*)(g_z + ((size_t)b*Nn + n)*DZ);
    #pragma unroll
    for (int i = 0; i < DZ/4; i++)
        zo[i] = make_float4(z[4*i], z[4*i+1], z[4*i+2], z[4*i+3]);

    // f_full
    #pragma unroll
    for (int f = 0; f < Ff; f++) {
        float s = sbs[f];
        for (int d = 0; d < DZ; d++) s += z[d]*sWs[d*Ff + f];
        g_ffull[((size_t)b*Nn + n)*Ff + f] = s;
    }

    // boundary value scatter (last occurrence wins, matching JAX .set)
    float bvv[Ff] = {0.f, 0.f, 0.f};
    for (int k = 0; k < 64; k++) {
        if (sdn[k] == n) {
            bvv[0] = sbv[k*Ff]; bvv[1] = sbv[k*Ff+1]; bvv[2] = sbv[k*Ff+2];
        }
    }

    // softmax over P per field, store duplicated pairs
    for (int f = 0; f < Ff; f++) {
        float lg[Pp];
        #pragma unroll
        for (int p = 0; p < Pp; p++) {
            float s = 0.f;
            for (int d = 0; d < DZ; d++) s += z[d]*sWp[d*57 + p*Ff + f];
            lg[p] = s;
        }
        lg[16] += bvv[f]; lg[17] += bvv[f]; lg[18] += bvv[f];
        float m = lg[0];
        #pragma unroll
        for (int p = 1; p < Pp; p++) m = fmaxf(m, lg[p]);
        float s = 0.f;
        #pragma unroll
        for (int p = 0; p < Pp; p++) { lg[p] = __expf(lg[p]-m); s += lg[p]; }
        float inv = 1.f/s;
        float2* wp = g_wpair + ((size_t)(b*Ff + f)*Nn + n)*PPAD;
        #pragma unroll
        for (int p = 0; p < Pp; p++) { float w = lg[p]*inv; wp[p] = make_float2(w, w); }
    }
}

// ------------- kernel 2: stage-1 projection  t[p,j] = sum_i W[p,i]*A[i,j] -------------
// grid: (4 j-tiles, 48 bf, 4 = mat*2+half), block 64, each thread 4 columns.
__global__ __launch_bounds__(64) void k_stage1(const float* __restrict__ Kl,
                                               const float* __restrict__ Ml)
{
    int bf   = blockIdx.y;
    int mat  = blockIdx.z >> 1;
    int half = blockIdx.z & 1;
    int j0   = blockIdx.x*256 + threadIdx.x*4;

    const float* src = (mat ? Ml : Kl) + (size_t)bf*Nn*Nn;
    const unsigned long long* wsrc =
        (const unsigned long long*)(g_wpair + (size_t)bf*Nn*PPAD);

    __shared__ __align__(16) unsigned long long sw[32*PPAD];

    unsigned long long acc[2*Pp];
    #pragma unroll
    for (int i = 0; i < 2*Pp; i++) acc[i] = 0ull;

    for (int ic = 0; ic < 16; ic++) {
        int ib = half*512 + ic*32;
        const unsigned long long* g = wsrc + (size_t)ib*PPAD;
        for (int idx = threadIdx.x; idx < 32*PPAD; idx += 64) sw[idx] = g[idx];
        __syncthreads();
        const float* kptr = src + (size_t)ib*Nn + j0;
        #pragma unroll 2
        for (int ii = 0; ii < 32; ii++) {
            float4 kv = *(const float4*)kptr;
            unsigned long long kx, ky;
            asm("mov.b64 %0, {%1,%2};" : "=l"(kx) : "f"(kv.x), "f"(kv.y));
            asm("mov.b64 %0, {%1,%2};" : "=l"(ky) : "f"(kv.z), "f"(kv.w));
            kptr += Nn;
            const unsigned long long* wrow = sw + ii*PPAD;
            #pragma unroll
            for (int p = 0; p < Pp; p++) {
                unsigned long long w = wrow[p];
                acc[2*p]   = ffma2(w, kx, acc[2*p]);
                acc[2*p+1] = ffma2(w, ky, acc[2*p+1]);
            }
        }
        __syncthreads();
    }

    float* tp = g_t + ((size_t)((bf*2 + mat)*2 + half))*Pp*Nn;
    #pragma unroll
    for (int p = 0; p < Pp; p++) {
        float2 a0 = ull2f2(acc[2*p]);
        float2 a1 = ull2f2(acc[2*p+1]);
        *(float4*)(tp + p*Nn + j0) = make_float4(a0.x, a0.y, a1.x, a1.y);
    }
}

// ------------- zp: mean(z) @ Wz + bf -------------
__global__ __launch_bounds__(64) void k_zp(const float* __restrict__ Wz,
                                           const float* __restrict__ bfv)
{
    int b = blockIdx.x, t = threadIdx.x;
    __shared__ float mz[DZ];
    float s = 0.f;
    const float* zb = g_z + (size_t)b*Nn*DZ + t;
    #pragma unroll 8
    for (int n = 0; n < Nn; n++) s += zb[(size_t)n*DZ];
    mz[t] = s * (1.f/Nn);
    __syncthreads();
    float a = bfv[t];
    for (int d = 0; d < DZ; d++) a += mz[d]*Wz[d*DH + t];
    g_zpb[b*DH + t] = a;
}

// ------------- f_latent -------------
__global__ __launch_bounds__(64) void k_flatent()
{
    int b = blockIdx.x, f = blockIdx.y, t = threadIdx.x;
    __shared__ float red[64][Pp];
    float acc[Pp];
    #pragma unroll
    for (int p = 0; p < Pp; p++) acc[p] = 0.f;
    const float2* w = g_wpair + (size_t)(b*Ff + f)*Nn*PPAD;
    for (int i = t; i < Nn; i += 64) {
        float fv = g_ffull[((size_t)b*Nn + i)*Ff + f];
        const float2* wr = w + (size_t)i*PPAD;
        #pragma unroll
        for (int p = 0; p < Pp; p++) acc[p] += wr[p].x * fv;
    }
    #pragma unroll
    for (int p = 0; p < Pp; p++) red[t][p] = acc[p];
    __syncthreads();
    if (t < Pp) {
        float s = 0.f;
        for (int k = 0; k < 64; k++) s += red[k][t];
        g_flat[(b*Ff + f)*Pp + t] = s * INV_SCALE;
    }
}

// ------------- stage-2: K_hat[p,q] = (t W^T)/scale + Dirichlet rows -------------
__global__ __launch_bounds__(384) void k_stage2()
{
    int bf = blockIdx.x;
    int mat = blockIdx.y;
    __shared__ float tS[Pp][129];
    __shared__ float wS[128][PPAD];
    int t = threadIdx.x;
    int p = t % Pp, q = t / Pp;
    bool act = (t < Pp*Pp);
    float acc = 0.f;
    const float* t0 = g_t + (size_t)((bf*2 + mat)*2)*Pp*Nn;
    const float* t1 = t0 + Pp*Nn;
    const float2* wsrc = g_wpair + (size_t)bf*Nn*PPAD;
    for (int jc = 0; jc < 8; jc++) {
        for (int idx = t; idx < Pp*128; idx += 384) {
            int pp = idx >> 7, jj = idx & 127;
            tS[pp][jj] = t0[pp*Nn + jc*128 + jj] + t1[pp*Nn + jc*128 + jj];
        }
        for (int idx = t; idx < 128*PPAD; idx += 384) {
            int jj = idx / PPAD, qq = idx % PPAD;
            wS[jj][qq] = wsrc[(size_t)jc*128*PPAD + idx].x;
        }
        __syncthreads();
        if (act) {
            #pragma unroll 8
            for (int jj = 0; jj < 128; jj++) acc += tS[p][jj]*wS[jj][q];
        }
        __syncthreads();
    }
    if (act) {
        float v = acc * INV_SCALE;
        if (p >= Pp-3) v = (p == q) ? 1.f : 0.f;
        g_khat[((size_t)mat*Bb*Ff + bf)*Pp*Pp + p*Pp + q] = v;
    }
}

// ------------- solver: 50 damped fixed-point iterations, one block per batch -------------
__global__ __launch_bounds__(192) void k_solver(const float* __restrict__ u_init,
                                                const float* __restrict__ Wf1,
                                                const float* __restrict__ Wf2)
{
    int b = blockIdx.x, t = threadIdx.x;
    __shared__ float Ks[Ff*Pp*Pp];
    __shared__ __align__(16) float w1[DH*8];  // per h: Wf1[0..5][h], zpb[h], pad
    __shared__ __align__(16) float w2[DH*4];  // per h: Wf2[h][0..2], pad
    __shared__ float srcs[64];
    __shared__ float flux[NEDGE*4];
    __shared__ float ua[64], ub[64];

    for (int i = t; i < Ff*Pp*Pp; i += 192)
        Ks[i] = g_khat[(size_t)b*Ff*Pp*Pp + i];
    for (int i = t; i < DH; i += 192) {
        w1[i*8+0] = Wf1[0*DH+i]; w1[i*8+1] = Wf1[1*DH+i]; w1[i*8+2] = Wf1[2*DH+i];
        w1[i*8+3] = Wf1[3*DH+i]; w1[i*8+4] = Wf1[4*DH+i]; w1[i*8+5] = Wf1[5*DH+i];
        w1[i*8+6] = g_zpb[b*DH+i]; w1[i*8+7] = 0.f;
        w2[i*4+0] = Wf2[i*Ff+0]; w2[i*4+1] = Wf2[i*Ff+1];
        w2[i*4+2] = Wf2[i*Ff+2]; w2[i*4+3] = 0.f;
    }
    if (t < Pp*Ff) ua[t] = u_init[b*Pp*Ff + t];
    __syncthreads();

    if (t < Pp*Ff) {  // src_term = M_hat @ f_latent (constant over iterations)
        int p = t / Ff, f = t % Ff;
        const float* mrow = g_khat + ((size_t)Bb*Ff + b*Ff + f)*Pp*Pp + p*Pp;
        const float* fl = g_flat + (b*Ff + f)*Pp;
        float s = 0.f;
        #pragma unroll
        for (int q = 0; q < Pp; q++) s += mrow[q]*fl[q];
        srcs[t] = s;
    }
    int ei = 0, ej = 0;
    if (t < NEDGE) {  // decode triu edge index
        int e = t, a = 0;
        while (e >= Pp-1-a) { e -= (Pp-1-a); a++; }
        ei = a; ej = a + 1 + e;
    }
    __syncthreads();

    float* cur = ua; float* nxt = ub;
    for (int it = 0; it < ITERS; it++) {
        if (t < NEDGE) {
            float u0 = cur[ei*Ff+0], u1 = cur[ei*Ff+1], u2 = cur[ei*Ff+2];
            float u3 = cur[ej*Ff+0], u4 = cur[ej*Ff+1], u5 = cur[ej*Ff+2];
            float a0 = 0.f, a1 = 0.f, a2 = 0.f;
            #pragma unroll 4
            for (int h = 0; h < DH; h++) {
                float4 A = *(const float4*)(w1 + h*8);
                float4 Bv = *(const float4*)(w1 + h*8 + 4);
                float s = Bv.z + u0*A.x + u1*A.y + u2*A.z + u3*A.w + u4*Bv.x + u5*Bv.y;
                float ax = fabsf(s);
                float tt = __expf(-2.f*ax);
                float r = __fdividef(1.f - tt, 1.f + tt);
                r = copysignf(r, s);
                float4 C = *(const float4*)(w2 + h*4);
                a0 += r*C.x; a1 += r*C.y; a2 += r*C.z;
            }
            flux[t*4+0] = a0; flux[t*4+1] = a1; flux[t*4+2] = a2;
        }
        __syncthreads();
        if (t < Pp*Ff) {
            int p = t / Ff, f = t % Ff;
            const float* kr = Ks + f*Pp*Pp + p*Pp;
            float diff = 0.f;
            #pragma unroll
            for (int q = 0; q < Pp; q++) diff += kr[q]*cur[q*Ff + f];
            float ft = 0.f;
            for (int q = 0; q < p; q++) {           // p == ej -> +flux
                int e = q*(Pp-1) - (q*(q-1))/2 + (p - q - 1);
                ft += flux[e*4 + f];
            }
            for (int q = p+1; q < Pp; q++) {        // p == ei -> -flux
                int e = p*(Pp-1) - (p*(p-1))/2 + (q - p - 1);
                ft -= flux[e*4 + f];
            }
            float r = diff - srcs[t] - ft;
            if (p >= Pp-3) r = cur[t] - ((p == Pp-3) ? 1.f : 0.f);
            nxt[t] = cur[t] - ALPHAc*r;
        }
        __syncthreads();
        float* tmp = cur; cur = nxt; nxt = tmp;
    }
    if (t < Pp*Ff) g_uhat[b*64 + t] = cur[t];
}

// ------------- u_fine = W^T u_coarse -------------
__global__ __launch_bounds__(128) void k_ufine(float* __restrict__ out)
{
    int b = blockIdx.y;
    int n = blockIdx.x*128 + threadIdx.x;
    __shared__ float us[64];
    if (threadIdx.x < 64) us[threadIdx.x] = g_uhat[b*64 + threadIdx.x];
    __syncthreads();
    float o[Ff];
    #pragma unroll
    for (int f = 0; f < Ff; f++) {
        const float2* wr = g_wpair + ((size_t)(b*Ff + f)*Nn + n)*PPAD;
        float s = 0.f;
        #pragma unroll
        for (int p = 0; p < Pp; p++) s += wr[p].x * us[p*Ff + f];
        o[f] = s;
    }
    float* op = out + ((size_t)b*Nn + n)*Ff;
    op[0] = o[0]; op[1] = o[1]; op[2] = o[2];
}

// ---------------- launch ----------------
extern "C" void kernel_launch(void* const* d_in, const int* in_sizes, int n_in,
                              void* d_out, int out_size)
{
    const float* tok   = (const float*)d_in[0];
    const float* Kl    = (const float*)d_in[1];
    const float* Ml    = (const float*)d_in[2];
    const int*   dn    = (const int*)  d_in[3];
    const float* bv    = (const float*)d_in[4];
    const float* u0    = (const float*)d_in[5];
    const float* W_enc = (const float*)d_in[6];
    const float* b_enc = (const float*)d_in[7];
    const float* W_src = (const float*)d_in[8];
    const float* b_src = (const float*)d_in[9];
    const float* W_pou = (const float*)d_in[10];
    const float* Wf1   = (const float*)d_in[11];
    const float* Wz    = (const float*)d_in[12];
    const float* bfv   = (const float*)d_in[13];
    const float* Wf2   = (const float*)d_in[14];
    float* out = (float*)d_out;

    k_encode <<<dim3(Nn/128, Bb),     128>>>(tok, dn, bv, W_enc, b_enc, W_src, b_src, W_pou);
    k_stage1 <<<dim3(4, Bb*Ff, 4),     64>>>(Kl, Ml);
    k_zp     <<<Bb,                    64>>>(Wz, bfv);
    k_flatent<<<dim3(Bb, Ff),          64>>>();
    k_stage2 <<<dim3(Bb*Ff, 2),       384>>>();
    k_solver <<<Bb,                   192>>>(u0, Wf1, Wf2);
    k_ufine  <<<dim3(Nn/128, Bb),     128>>>(out);
}

// round 11
// speedup vs baseline: 1.7590x; 1.7590x over previous
#include <cuda_runtime.h>
#include <math.h>

#define Bb   16
#define Nn   1024
#define DIN  32
#define DZ   64
#define DH   64
#define Ff   3
#define Pp   19
#define PPAD 20
#define NEDGE 171
#define ITERS 50
#define ALPHAc 0.1f
#define INV_SCALE (19.0f/1024.0f)

// ---------------- device scratch (static; no allocations) ----------------
__device__ __align__(16) float2 g_wpair[(size_t)Bb*Ff*Nn*PPAD]; // {w,w} pairs for FFMA2 (stage1)
__device__ __align__(16) float  g_wc[(size_t)Bb*Ff*Nn*PPAD];    // compact weights (stage2/ufine)
__device__ __align__(16) float  g_t[(size_t)192*Pp*Nn];         // stage-1 partials
__device__ __align__(16) float  g_khat[2*Bb*Ff*Pp*Pp];          // [mat][b][f][p][q]
__device__ __align__(16) float  g_zpart[Bb*8*DZ];               // per-block z partial sums
__device__ __align__(16) float  g_flpart[Bb*8*64];              // per-block f_latent partials (57 used)
__device__ __align__(16) float  g_uhat[Bb*64];

// packed f32x2 FMA (Blackwell FFMA2)
__device__ __forceinline__ unsigned long long ffma2(unsigned long long a,
                                                    unsigned long long b,
                                                    unsigned long long c) {
    unsigned long long d;
    asm("fma.rn.f32x2 %0, %1, %2, %3;" : "=l"(d) : "l"(a), "l"(b), "l"(c));
    return d;
}
__device__ __forceinline__ float2 ull2f2(unsigned long long v) {
    float2 r;
    asm("mov.b64 {%0,%1}, %2;" : "=f"(r.x), "=f"(r.y) : "l"(v));
    return r;
}
__device__ __forceinline__ float warp_sum(float v) {
    v += __shfl_xor_sync(0xffffffffu, v, 16);
    v += __shfl_xor_sync(0xffffffffu, v, 8);
    v += __shfl_xor_sync(0xffffffffu, v, 4);
    v += __shfl_xor_sync(0xffffffffu, v, 2);
    v += __shfl_xor_sync(0xffffffffu, v, 1);
    return v;
}

// ---------------- kernel 1: encoder + POU softmax + fused partial reductions ----------------
__global__ __launch_bounds__(128) void k_encode(
    const float* __restrict__ tok, const int* __restrict__ dn,
    const float* __restrict__ bv,
    const float* __restrict__ W_enc, const float* __restrict__ b_enc,
    const float* __restrict__ W_src, const float* __restrict__ b_src,
    const float* __restrict__ W_pou)
{
    __shared__ float sWe[DIN*DZ];
    __shared__ float sWp[DZ*57];
    __shared__ float sWs[DZ*Ff];
    __shared__ float sbe[DZ];
    __shared__ float sbs[Ff];
    __shared__ int   sdn[64];
    __shared__ float sbv[64*Ff];
    __shared__ float sW4[4][DZ];     // warp partials for z-mean
    __shared__ float sFl[4][Pp];     // warp partials for f_latent (per f)

    int b = blockIdx.y;
    int tid = threadIdx.x;
    int wid = tid >> 5, lane = tid & 31;
    for (int i = tid; i < DIN*DZ; i += 128) sWe[i] = W_enc[i];
    for (int i = tid; i < DZ*57;  i += 128) sWp[i] = W_pou[i];
    for (int i = tid; i < DZ*Ff;  i += 128) sWs[i] = W_src[i];
    if (tid < DZ) sbe[tid] = b_enc[tid];
    if (tid < Ff) sbs[tid] = b_src[tid];
    if (tid < 64) sdn[tid] = dn[b*64 + tid];
    for (int i = tid; i < 64*Ff; i += 128) sbv[i] = bv[b*64*Ff + i];
    __syncthreads();

    int n = blockIdx.x*128 + tid;

    float x[DIN];
    const float4* xp = (const float4*)(tok + ((size_t)b*Nn + n)*DIN);
    #pragma unroll
    for (int i = 0; i < DIN/4; i++) {
        float4 v = xp[i];
        x[4*i] = v.x; x[4*i+1] = v.y; x[4*i+2] = v.z; x[4*i+3] = v.w;
    }

    float z[DZ];
    #pragma unroll
    for (int d = 0; d < DZ; d++) z[d] = sbe[d];
    for (int k = 0; k < DIN; k++) {
        float xv = x[k];
        const float* wr = sWe + k*DZ;
        #pragma unroll
        for (int d = 0; d < DZ; d++) z[d] += xv * wr[d];
    }
    #pragma unroll
    for (int d = 0; d < DZ; d++) z[d] = tanhf(z[d]);

    // z-mean partial (deterministic: fixed warp/block reduction order)
    #pragma unroll
    for (int d = 0; d < DZ; d++) {
        float v = warp_sum(z[d]);
        if (lane == 0) sW4[wid][d] = v;
    }
    __syncthreads();
    if (tid < DZ)
        g_zpart[((size_t)b*8 + blockIdx.x)*DZ + tid] =
            sW4[0][tid] + sW4[1][tid] + sW4[2][tid] + sW4[3][tid];

    // f_full
    float ffull[Ff];
    #pragma unroll
    for (int f = 0; f < Ff; f++) {
        float s = sbs[f];
        for (int d = 0; d < DZ; d++) s += z[d]*sWs[d*Ff + f];
        ffull[f] = s;
    }

    // boundary value scatter (last occurrence wins, matching JAX .set)
    float bvv[Ff] = {0.f, 0.f, 0.f};
    for (int k = 0; k < 64; k++) {
        if (sdn[k] == n) {
            bvv[0] = sbv[k*Ff]; bvv[1] = sbv[k*Ff+1]; bvv[2] = sbv[k*Ff+2];
        }
    }

    // softmax over P per field + weight stores + f_latent partials
    for (int f = 0; f < Ff; f++) {
        float lg[Pp];
        #pragma unroll
        for (int p = 0; p < Pp; p++) {
            float s = 0.f;
            for (int d = 0; d < DZ; d++) s += z[d]*sWp[d*57 + p*Ff + f];
            lg[p] = s;
        }
        lg[16] += bvv[f]; lg[17] += bvv[f]; lg[18] += bvv[f];
        float m = lg[0];
        #pragma unroll
        for (int p = 1; p < Pp; p++) m = fmaxf(m, lg[p]);
        float s = 0.f;
        #pragma unroll
        for (int p = 0; p < Pp; p++) { lg[p] = __expf(lg[p]-m); s += lg[p]; }
        float inv = 1.f/s;
        float2* wp = g_wpair + ((size_t)(b*Ff + f)*Nn + n)*PPAD;
        float*  wc = g_wc    + ((size_t)(b*Ff + f)*Nn + n)*PPAD;
        #pragma unroll
        for (int p = 0; p < Pp; p++) {
            float w = lg[p]*inv;
            lg[p] = w;
            wp[p] = make_float2(w, w);
            wc[p] = w;
        }
        // f_latent partial for this field
        __syncthreads();
        #pragma unroll
        for (int p = 0; p < Pp; p++) {
            float v = warp_sum(lg[p]*ffull[f]);
            if (lane == 0) sFl[wid][p] = v;
        }
        __syncthreads();
        if (tid < Pp)
            g_flpart[((size_t)b*8 + blockIdx.x)*64 + tid*Ff + f] =
                sFl[0][tid] + sFl[1][tid] + sFl[2][tid] + sFl[3][tid];
    }
}

// ------------- kernel 2: stage-1 projection  t[p,j] = sum_i W[p,i]*A[i,j] -------------
__global__ __launch_bounds__(64) void k_stage1(const float* __restrict__ Kl,
                                               const float* __restrict__ Ml)
{
    int bf   = blockIdx.y;
    int mat  = blockIdx.z >> 1;
    int half = blockIdx.z & 1;
    int j0   = blockIdx.x*256 + threadIdx.x*4;

    const float* src = (mat ? Ml : Kl) + (size_t)bf*Nn*Nn;
    const unsigned long long* wsrc =
        (const unsigned long long*)(g_wpair + (size_t)bf*Nn*PPAD);

    __shared__ __align__(16) unsigned long long sw[32*PPAD];

    unsigned long long acc[2*Pp];
    #pragma unroll
    for (int i = 0; i < 2*Pp; i++) acc[i] = 0ull;

    for (int ic = 0; ic < 16; ic++) {
        int ib = half*512 + ic*32;
        const unsigned long long* g = wsrc + (size_t)ib*PPAD;
        for (int idx = threadIdx.x; idx < 32*PPAD; idx += 64) sw[idx] = g[idx];
        __syncthreads();
        const float* kptr = src + (size_t)ib*Nn + j0;
        #pragma unroll 4
        for (int ii = 0; ii < 32; ii++) {
            float4 kv = *(const float4*)kptr;
            unsigned long long kx, ky;
            asm("mov.b64 %0, {%1,%2};" : "=l"(kx) : "f"(kv.x), "f"(kv.y));
            asm("mov.b64 %0, {%1,%2};" : "=l"(ky) : "f"(kv.z), "f"(kv.w));
            kptr += Nn;
            const unsigned long long* wrow = sw + ii*PPAD;
            #pragma unroll
            for (int p = 0; p < Pp; p++) {
                unsigned long long w = wrow[p];
                acc[2*p]   = ffma2(w, kx, acc[2*p]);
                acc[2*p+1] = ffma2(w, ky, acc[2*p+1]);
            }
        }
        __syncthreads();
    }

    float* tp = g_t + ((size_t)((bf*2 + mat)*2 + half))*Pp*Nn;
    #pragma unroll
    for (int p = 0; p < Pp; p++) {
        float2 a0 = ull2f2(acc[2*p]);
        float2 a1 = ull2f2(acc[2*p+1]);
        *(float4*)(tp + p*Nn + j0) = make_float4(a0.x, a0.y, a1.x, a1.y);
    }
}

// ------------- stage-2: K_hat[p,q] = (t W^T)/scale + Dirichlet rows -------------
__global__ __launch_bounds__(384) void k_stage2()
{
    int bf = blockIdx.x;
    int mat = blockIdx.y;
    __shared__ float tS[Pp][129];
    __shared__ float wS[128*PPAD];
    int t = threadIdx.x;
    int p = t % Pp, q = t / Pp;
    bool act = (t < Pp*Pp);
    float acc = 0.f;
    const float* t0 = g_t + (size_t)((bf*2 + mat)*2)*Pp*Nn;
    const float* t1 = t0 + Pp*Nn;
    const float* wsrc0 = g_wc + (size_t)bf*Nn*PPAD;
    for (int jc = 0; jc < 8; jc++) {
        for (int idx = t; idx < Pp*128; idx += 384) {
            int pp = idx >> 7, jj = idx & 127;
            tS[pp][jj] = t0[pp*Nn + jc*128 + jj] + t1[pp*Nn + jc*128 + jj];
        }
        const float* wsrc = wsrc0 + (size_t)jc*128*PPAD;
        for (int idx = t; idx < 128*PPAD; idx += 384) wS[idx] = wsrc[idx];
        __syncthreads();
        if (act) {
            #pragma unroll 8
            for (int jj = 0; jj < 128; jj++) acc += tS[p][jj]*wS[jj*PPAD + q];
        }
        __syncthreads();
    }
    if (act) {
        float v = acc * INV_SCALE;
        if (p >= Pp-3) v = (p == q) ? 1.f : 0.f;
        g_khat[((size_t)mat*Bb*Ff + bf)*Pp*Pp + p*Pp + q] = v;
    }
}

// ------------- solver: prologue reductions + 50 damped fixed-point iterations -------------
__global__ __launch_bounds__(192) void k_solver(const float* __restrict__ u_init,
                                                const float* __restrict__ Wf1,
                                                const float* __restrict__ Wf2,
                                                const float* __restrict__ Wz,
                                                const float* __restrict__ bfv)
{
    int b = blockIdx.x, t = threadIdx.x;
    __shared__ float Ks[Ff*Pp*Pp];
    __shared__ __align__(16) float w1[DH*8];  // per h: Wf1[0..5][h], zp[h], pad
    __shared__ __align__(16) float w2[DH*4];  // per h: Wf2[h][0..2], pad
    __shared__ float srcs[64];
    __shared__ float flux[NEDGE*4];
    __shared__ float ua[64], ub[64];
    __shared__ float mz[DZ];
    __shared__ float sfl[64];

    for (int i = t; i < Ff*Pp*Pp; i += 192)
        Ks[i] = g_khat[(size_t)b*Ff*Pp*Pp + i];
    for (int i = t; i < DH; i += 192) {
        w1[i*8+0] = Wf1[0*DH+i]; w1[i*8+1] = Wf1[1*DH+i]; w1[i*8+2] = Wf1[2*DH+i];
        w1[i*8+3] = Wf1[3*DH+i]; w1[i*8+4] = Wf1[4*DH+i]; w1[i*8+5] = Wf1[5*DH+i];
        w1[i*8+7] = 0.f;
        w2[i*4+0] = Wf2[i*Ff+0]; w2[i*4+1] = Wf2[i*Ff+1];
        w2[i*4+2] = Wf2[i*Ff+2]; w2[i*4+3] = 0.f;
    }
    if (t < Pp*Ff) ua[t] = u_init[b*Pp*Ff + t];
    // reduce z-mean and f_latent partials (deterministic fixed order)
    if (t < DZ) {
        float s = 0.f;
        #pragma unroll
        for (int k = 0; k < 8; k++) s += g_zpart[((size_t)b*8 + k)*DZ + t];
        mz[t] = s * (1.f/Nn);
    } else if (t >= 64 && t < 64 + Pp*Ff) {
        int k = t - 64;
        float s = 0.f;
        #pragma unroll
        for (int j = 0; j < 8; j++) s += g_flpart[((size_t)b*8 + j)*64 + k];
        sfl[k] = s * INV_SCALE;
    }
    __syncthreads();

    if (t < DH) {  // zp = mean(z) @ Wz + bf  -> slot 6 of w1
        float a = bfv[t];
        #pragma unroll 8
        for (int d = 0; d < DZ; d++) a += mz[d]*Wz[d*DH + t];
        w1[t*8+6] = a;
    } else if (t >= 64 && t < 64 + Pp*Ff) {  // src_term = M_hat @ f_latent
        int k = t - 64;
        int p = k / Ff, f = k % Ff;
        const float* mrow = g_khat + ((size_t)Bb*Ff + b*Ff + f)*Pp*Pp + p*Pp;
        float s = 0.f;
        #pragma unroll
        for (int q = 0; q < Pp; q++) s += mrow[q]*sfl[q*Ff + f];
        srcs[k] = s;
    }
    int ei = 0, ej = 0;
    if (t < NEDGE) {  // decode triu edge index
        int e = t, a = 0;
        while (e >= Pp-1-a) { e -= (Pp-1-a); a++; }
        ei = a; ej = a + 1 + e;
    }
    __syncthreads();

    float* cur = ua; float* nxt = ub;
    for (int it = 0; it < ITERS; it++) {
        if (t < NEDGE) {
            float u0 = cur[ei*Ff+0], u1 = cur[ei*Ff+1], u2 = cur[ei*Ff+2];
            float u3 = cur[ej*Ff+0], u4 = cur[ej*Ff+1], u5 = cur[ej*Ff+2];
            float a0 = 0.f, a1 = 0.f, a2 = 0.f;
            #pragma unroll 4
            for (int h = 0; h < DH; h++) {
                float4 A = *(const float4*)(w1 + h*8);
                float4 Bv = *(const float4*)(w1 + h*8 + 4);
                float s = Bv.z + u0*A.x + u1*A.y + u2*A.z + u3*A.w + u4*Bv.x + u5*Bv.y;
                float r;
                asm("tanh.approx.f32 %0, %1;" : "=f"(r) : "f"(s));
                float4 C = *(const float4*)(w2 + h*4);
                a0 += r*C.x; a1 += r*C.y; a2 += r*C.z;
            }
            flux[t*4+0] = a0; flux[t*4+1] = a1; flux[t*4+2] = a2;
        }
        __syncthreads();
        if (t < Pp*Ff) {
            int p = t / Ff, f = t % Ff;
            const float* kr = Ks + f*Pp*Pp + p*Pp;
            float diff = 0.f;
            #pragma unroll
            for (int q = 0; q < Pp; q++) diff += kr[q]*cur[q*Ff + f];
            float ft = 0.f;
            for (int q = 0; q < p; q++) {           // p == ej -> +flux
                int e = q*(Pp-1) - (q*(q-1))/2 + (p - q - 1);
                ft += flux[e*4 + f];
            }
            for (int q = p+1; q < Pp; q++) {        // p == ei -> -flux
                int e = p*(Pp-1) - (p*(p-1))/2 + (q - p - 1);
                ft -= flux[e*4 + f];
            }
            float r = diff - srcs[t] - ft;
            if (p >= Pp-3) r = cur[t] - ((p == Pp-3) ? 1.f : 0.f);
            nxt[t] = cur[t] - ALPHAc*r;
        }
        __syncthreads();
        float* tmp = cur; cur = nxt; nxt = tmp;
    }
    if (t < Pp*Ff) g_uhat[b*64 + t] = cur[t];
}

// ------------- u_fine = W^T u_coarse (compact weights, vectorized) -------------
__global__ __launch_bounds__(128) void k_ufine(float* __restrict__ out)
{
    int b = blockIdx.y;
    int tid = threadIdx.x;
    int n = blockIdx.x*128 + tid;
    __shared__ float us[64];
    __shared__ __align__(16) float so[384];
    if (tid < 64) us[tid] = g_uhat[b*64 + tid];
    __syncthreads();
    float o[Ff];
    #pragma unroll
    for (int f = 0; f < Ff; f++) {
        const float4* wv = (const float4*)(g_wc + ((size_t)(b*Ff + f)*Nn + n)*PPAD);
        float acc = 0.f;
        #pragma unroll
        for (int k = 0; k < 5; k++) {
            float4 w4 = wv[k];
            int p0 = 4*k;
            acc += w4.x*us[p0*Ff + f];
            if (p0+1 < Pp) acc += w4.y*us[(p0+1)*Ff + f];
            if (p0+2 < Pp) acc += w4.z*us[(p0+2)*Ff + f];
            if (p0+3 < Pp) acc += w4.w*us[(p0+3)*Ff + f];
        }
        o[f] = acc;
    }
    so[tid*3+0] = o[0]; so[tid*3+1] = o[1]; so[tid*3+2] = o[2];
    __syncthreads();
    float4* ob = (float4*)(out + ((size_t)b*Nn + blockIdx.x*128)*Ff);
    if (tid < 96) ob[tid] = ((const float4*)so)[tid];
}

// ---------------- launch ----------------
extern "C" void kernel_launch(void* const* d_in, const int* in_sizes, int n_in,
                              void* d_out, int out_size)
{
    const float* tok   = (const float*)d_in[0];
    const float* Kl    = (const float*)d_in[1];
    const float* Ml    = (const float*)d_in[2];
    const int*   dn    = (const int*)  d_in[3];
    const float* bv    = (const float*)d_in[4];
    const float* u0    = (const float*)d_in[5];
    const float* W_enc = (const float*)d_in[6];
    const float* b_enc = (const float*)d_in[7];
    const float* W_src = (const float*)d_in[8];
    const float* b_src = (const float*)d_in[9];
    const float* W_pou = (const float*)d_in[10];
    const float* Wf1   = (const float*)d_in[11];
    const float* Wz    = (const float*)d_in[12];
    const float* bfv   = (const float*)d_in[13];
    const float* Wf2   = (const float*)d_in[14];
    float* out = (float*)d_out;

    k_encode <<<dim3(Nn/128, Bb),  128>>>(tok, dn, bv, W_enc, b_enc, W_src, b_src, W_pou);
    k_stage1 <<<dim3(4, Bb*Ff, 4),  64>>>(Kl, Ml);
    k_stage2 <<<dim3(Bb*Ff, 2),    384>>>();
    k_solver <<<Bb,                192>>>(u0, Wf1, Wf2, Wz, bfv);
    k_ufine  <<<dim3(Nn/128, Bb),  128>>>(out);
}